// round 6
// baseline (speedup 1.0000x reference)
#include <cuda_runtime.h>

#define N_NODES 100000
#define N_EDGES 3200000
#define M 24
#define HID 32
#define OUT 16
#define ZC (3*M + OUT)   // 88

// ---------------- scratch (device globals; no allocation allowed) ----------
__device__ unsigned int        g_mask[N_NODES];        // packed binary features
__device__ unsigned long long  g_cnt[N_NODES * 3];     // 24 x 8-bit counters per node
__device__ int                 g_deg[N_NODES];         // in-degree
__device__ float4              g_h4[N_NODES * (HID/4)];   // h rows (N x 32 f32)
__device__ float               g_s2[N_NODES * HID];       // sum of h over neighbors
__device__ int                 g_is64;                 // edge dtype flag

__device__ __forceinline__ int clampN(long long v) {
    int x = (int)v;
    if (x < 0) x = 0;
    if (x >= N_NODES) x = N_NODES - 1;
    return x;
}

// Spread 8 bits of v into 8 bytes: byte (7-j) of result = bit j of v.
__device__ __forceinline__ unsigned long long spread8(unsigned v) {
    return (((unsigned long long)v * 0x8040201008040201ULL) >> 7)
           & 0x0101010101010101ULL;
}

// Fetch edge endpoints under either int32 or int64 storage.
__device__ __forceinline__ void edge_rc(const void* ei, int e, int is64,
                                        int& r, int& c) {
    if (is64) {
        const long long* p = (const long long*)ei;
        r = clampN(p[e]);
        c = clampN(p[N_EDGES + e]);
    } else {
        const int* p = (const int*)ei;
        r = clampN(p[e]);
        c = clampN(p[N_EDGES + e]);
    }
}

// ---------------- kernel 0: probe edge dtype -------------------------------
__global__ void k_probe(const long long* __restrict__ ei) {
    // Real int64 node ids are < N_NODES. If the buffer is int32, an int64
    // read pairs two ids: value = lo + hi*2^32 with hi ~ U[0,100000) -> huge.
    int ok64 = 1;
    for (int i = 0; i < 8; i++) {
        long long v = ei[i];
        if (v < 0 || v >= (long long)N_NODES) ok64 = 0;
    }
    g_is64 = ok64;
}

// ---------------- kernel 1: pack masks + zero scratch ----------------------
__global__ void k_init(const float* __restrict__ xb) {
    int n = blockIdx.x * blockDim.x + threadIdx.x;
    if (n >= N_NODES) return;
    const float4* xr = (const float4*)(xb + (size_t)n * M);
    unsigned m = 0;
#pragma unroll
    for (int q = 0; q < 6; q++) {
        float4 v = xr[q];
        if (v.x > 0.5f) m |= 1u << (4*q + 0);
        if (v.y > 0.5f) m |= 1u << (4*q + 1);
        if (v.z > 0.5f) m |= 1u << (4*q + 2);
        if (v.w > 0.5f) m |= 1u << (4*q + 3);
    }
    g_mask[n] = m;
    g_cnt[3*n + 0] = 0ULL;
    g_cnt[3*n + 1] = 0ULL;
    g_cnt[3*n + 2] = 0ULL;
    g_deg[n] = 0;
    float4 z4 = make_float4(0.f, 0.f, 0.f, 0.f);
    float4* s4 = (float4*)(g_s2 + (size_t)n * HID);
#pragma unroll
    for (int q = 0; q < HID/4; q++) s4[q] = z4;
}

// ---------------- kernel 2: edge pass 1 (binary feature scatter) -----------
__global__ void k_edge1(const void* __restrict__ ei) {
    int e = blockIdx.x * blockDim.x + threadIdx.x;
    if (e >= N_EDGES) return;
    int is64 = g_is64;
    int r, c;
    edge_rc(ei, e, is64, r, c);
    unsigned m = g_mask[r];
    unsigned long long w0 = spread8( m         & 0xffu);
    unsigned long long w1 = spread8((m >>  8)  & 0xffu);
    unsigned long long w2 = spread8((m >> 16)  & 0xffu);
    atomicAdd(&g_cnt[3*c + 0], w0);
    atomicAdd(&g_cnt[3*c + 1], w1);
    atomicAdd(&g_cnt[3*c + 2], w2);
    atomicAdd(&g_deg[c], 1);
}

// ---------------- kernel 3: node pass 1 (SAGE layer 1 -> h) ----------------
__global__ __launch_bounds__(128)
void k_node1(const float* __restrict__ w1l, const float* __restrict__ b1,
             const float* __restrict__ w1r) {
    __shared__ float s_l[HID*M], s_r[HID*M], s_b[HID];
    for (int i = threadIdx.x; i < HID*M; i += blockDim.x) {
        s_l[i] = w1l[i];
        s_r[i] = w1r[i];
    }
    for (int i = threadIdx.x; i < HID; i += blockDim.x) s_b[i] = b1[i];
    __syncthreads();

    int n = blockIdx.x * blockDim.x + threadIdx.x;
    if (n >= N_NODES) return;

    unsigned m = g_mask[n];
    int deg = g_deg[n];
    float inv = 1.0f / (float)(deg > 0 ? deg : 1);
    unsigned long long w[3];
    w[0] = g_cnt[3*n + 0];
    w[1] = g_cnt[3*n + 1];
    w[2] = g_cnt[3*n + 2];

    float ff[M], fx[M];
#pragma unroll
    for (int j = 0; j < M; j++) {
        int g = j >> 3, jj = j & 7;
        unsigned c = (unsigned)((w[g] >> (8 * (7 - jj))) & 0xffULL);
        ff[j] = (float)c * inv;
        fx[j] = (float)((m >> j) & 1u);
    }

    float hrow[HID];
#pragma unroll
    for (int i = 0; i < HID; i++) {
        float a = s_b[i];
#pragma unroll
        for (int j = 0; j < M; j++)
            a += ff[j] * s_l[i*M + j] + fx[j] * s_r[i*M + j];
        hrow[i] = fmaxf(a, 0.0f);
    }
    float4* hr4 = &g_h4[(size_t)n * (HID/4)];
#pragma unroll
    for (int q = 0; q < HID/4; q++)
        hr4[q] = make_float4(hrow[4*q+0], hrow[4*q+1], hrow[4*q+2], hrow[4*q+3]);
}

// ---------------- kernel 4: edge pass 2 (h scatter, scalar REDs) -----------
__global__ void k_edge2(const void* __restrict__ ei) {
    int e = blockIdx.x * blockDim.x + threadIdx.x;
    if (e >= N_EDGES) return;
    int is64 = g_is64;
    int r, c;
    edge_rc(ei, e, is64, r, c);
    const float4* hr = &g_h4[(size_t)r * (HID/4)];
    float*        sd = g_s2 + (size_t)c * HID;
#pragma unroll
    for (int q = 0; q < HID/4; q++) {
        float4 v = hr[q];
        atomicAdd(sd + 4*q + 0, v.x);
        atomicAdd(sd + 4*q + 1, v.y);
        atomicAdd(sd + 4*q + 2, v.z);
        atomicAdd(sd + 4*q + 3, v.w);
    }
}

// ---------------- kernel 5: node pass 2 (layer 2 + feats + head) -----------
__global__ __launch_bounds__(128)
void k_node2(const float* __restrict__ w2l, const float* __restrict__ b2,
             const float* __restrict__ w2r, const float* __restrict__ hw,
             const float* __restrict__ hb, float* __restrict__ out,
             int write_z) {
    __shared__ float s_l[OUT*HID], s_r[OUT*HID], s_b[OUT], s_hw[ZC], s_hb;
    for (int i = threadIdx.x; i < OUT*HID; i += blockDim.x) {
        s_l[i] = w2l[i];
        s_r[i] = w2r[i];
    }
    for (int i = threadIdx.x; i < OUT; i += blockDim.x) s_b[i] = b2[i];
    for (int i = threadIdx.x; i < ZC;  i += blockDim.x) s_hw[i] = hw[i];
    if (threadIdx.x == 0) s_hb = hb[0];
    __syncthreads();

    int n = blockIdx.x * blockDim.x + threadIdx.x;
    if (n >= N_NODES) return;

    unsigned m = g_mask[n];
    int deg = g_deg[n];
    float inv = 1.0f / (float)(deg > 0 ? deg : 1);
    unsigned long long w[3];
    w[0] = g_cnt[3*n + 0];
    w[1] = g_cnt[3*n + 1];
    w[2] = g_cnt[3*n + 2];

    float y = s_hb;
    float4* zrow = (float4*)(out + N_NODES + (size_t)n * ZC);

    float ff[M];
#pragma unroll
    for (int j = 0; j < M; j++) {
        int g = j >> 3, jj = j & 7;
        unsigned c = (unsigned)((w[g] >> (8 * (7 - jj))) & 0xffULL);
        ff[j] = (float)c * inv;
    }
#pragma unroll
    for (int q = 0; q < M/4; q++) {
        float x0 = (float)((m >> (4*q+0)) & 1u);
        float x1 = (float)((m >> (4*q+1)) & 1u);
        float x2 = (float)((m >> (4*q+2)) & 1u);
        float x3 = (float)((m >> (4*q+3)) & 1u);
        float f0 = ff[4*q+0], f1 = ff[4*q+1], f2 = ff[4*q+2], f3 = ff[4*q+3];
        if (write_z) {
            zrow[q]           = make_float4(x0, x1, x2, x3);
            zrow[M/4 + q]     = make_float4(f0, f1, f2, f3);
            zrow[2*(M/4) + q] = make_float4(x0*f0, x1*f1, x2*f2, x3*f3);
        }
        y += x0*s_hw[4*q+0] + x1*s_hw[4*q+1] + x2*s_hw[4*q+2] + x3*s_hw[4*q+3];
        y += f0*s_hw[M+4*q+0] + f1*s_hw[M+4*q+1] + f2*s_hw[M+4*q+2] + f3*s_hw[M+4*q+3];
        y += x0*f0*s_hw[2*M+4*q+0] + x1*f1*s_hw[2*M+4*q+1]
           + x2*f2*s_hw[2*M+4*q+2] + x3*f3*s_hw[2*M+4*q+3];
    }

    float hrow[HID], ag[HID];
    const float4* h4 = &g_h4[(size_t)n * (HID/4)];
    const float4* s4 = (const float4*)(g_s2 + (size_t)n * HID);
#pragma unroll
    for (int q = 0; q < HID/4; q++) {
        float4 hv = h4[q], sv = s4[q];
        hrow[4*q+0] = hv.x; hrow[4*q+1] = hv.y; hrow[4*q+2] = hv.z; hrow[4*q+3] = hv.w;
        ag[4*q+0] = sv.x*inv; ag[4*q+1] = sv.y*inv; ag[4*q+2] = sv.z*inv; ag[4*q+3] = sv.w*inv;
    }

    float emb[OUT];
#pragma unroll
    for (int i = 0; i < OUT; i++) {
        float a = s_b[i];
#pragma unroll
        for (int j = 0; j < HID; j++)
            a += ag[j] * s_l[i*HID + j] + hrow[j] * s_r[i*HID + j];
        a = fmaxf(a, 0.0f);
        emb[i] = a;
        y += a * s_hw[3*M + i];
    }
    if (write_z) {
#pragma unroll
        for (int q = 0; q < OUT/4; q++)
            zrow[3*(M/4) + q] = make_float4(emb[4*q+0], emb[4*q+1], emb[4*q+2], emb[4*q+3]);
    }

    out[n] = y;
}

// ---------------- launch --------------------------------------------------
extern "C" void kernel_launch(void* const* d_in, const int* in_sizes, int n_in,
                              void* d_out, int out_size) {
    const float* x_bin = (const float*)d_in[0];
    const void*  ei    = d_in[1];
    const float* w1l   = (const float*)d_in[2];
    const float* b1    = (const float*)d_in[3];
    const float* w1r   = (const float*)d_in[4];
    const float* w2l   = (const float*)d_in[5];
    const float* b2    = (const float*)d_in[6];
    const float* w2r   = (const float*)d_in[7];
    const float* hw    = (const float*)d_in[8];
    const float* hb    = (const float*)d_in[9];
    float* out = (float*)d_out;

    int write_z = (out_size >= N_NODES + N_NODES * ZC) ? 1 : 0;

    int nb_n256 = (N_NODES + 255) / 256;
    int nb_n128 = (N_NODES + 127) / 128;
    int nb_e    = (N_EDGES + 255) / 256;

    k_probe<<<1, 1>>>((const long long*)ei);
    k_init <<<nb_n256, 256>>>(x_bin);
    k_edge1<<<nb_e,    256>>>(ei);
    k_node1<<<nb_n128, 128>>>(w1l, b1, w1r);
    k_edge2<<<nb_e,    256>>>(ei);
    k_node2<<<nb_n128, 128>>>(w2l, b2, w2r, hw, hb, out, write_z);
}

// round 8
// speedup vs baseline: 1.8359x; 1.8359x over previous
#include <cuda_runtime.h>

#define N_NODES 100000
#define N_EDGES 3200000
#define M 24
#define HID 32
#define OUT 16
#define ZC (3*M + OUT)   // 88

// ---------------- scratch (device globals; no allocation allowed) ----------
__device__ unsigned int        g_mask[N_NODES];        // packed binary features
__device__ unsigned long long  g_cnt[N_NODES * 3];     // 24 x 8-bit counters per node
__device__ int                 g_deg[N_NODES];         // in-degree
__device__ float4              g_h4[N_NODES * (HID/4)];   // h rows (N x 32 f32)
__device__ float4              g_s2_4[N_NODES * (HID/4)]; // neighbor-sum of h (16B aligned)
__device__ int                 g_is64;                 // edge dtype flag

__device__ __forceinline__ int clampN(long long v) {
    int x = (int)v;
    if (x < 0) x = 0;
    if (x >= N_NODES) x = N_NODES - 1;
    return x;
}

// Spread 8 bits of v into 8 bytes: byte (7-j) of result = bit j of v.
__device__ __forceinline__ unsigned long long spread8(unsigned v) {
    return (((unsigned long long)v * 0x8040201008040201ULL) >> 7)
           & 0x0101010101010101ULL;
}

// Fetch edge endpoints under either int32 or int64 storage.
__device__ __forceinline__ void edge_rc(const void* ei, int e, int is64,
                                        int& r, int& c) {
    if (is64) {
        const long long* p = (const long long*)ei;
        r = clampN(p[e]);
        c = clampN(p[N_EDGES + e]);
    } else {
        const int* p = (const int*)ei;
        r = clampN(p[e]);
        c = clampN(p[N_EDGES + e]);
    }
}

// ---------------- kernel 0: probe edge dtype -------------------------------
__global__ void k_probe(const long long* __restrict__ ei) {
    int ok64 = 1;
    for (int i = 0; i < 8; i++) {
        long long v = ei[i];
        if (v < 0 || v >= (long long)N_NODES) ok64 = 0;
    }
    g_is64 = ok64;
}

// ---------------- kernel 1: pack masks + zero scratch ----------------------
__global__ void k_init(const float* __restrict__ xb) {
    int n = blockIdx.x * blockDim.x + threadIdx.x;
    if (n >= N_NODES) return;
    const float4* xr = (const float4*)(xb + (size_t)n * M);
    unsigned m = 0;
#pragma unroll
    for (int q = 0; q < 6; q++) {
        float4 v = xr[q];
        if (v.x > 0.5f) m |= 1u << (4*q + 0);
        if (v.y > 0.5f) m |= 1u << (4*q + 1);
        if (v.z > 0.5f) m |= 1u << (4*q + 2);
        if (v.w > 0.5f) m |= 1u << (4*q + 3);
    }
    g_mask[n] = m;
    g_cnt[3*n + 0] = 0ULL;
    g_cnt[3*n + 1] = 0ULL;
    g_cnt[3*n + 2] = 0ULL;
    g_deg[n] = 0;
    float4 z4 = make_float4(0.f, 0.f, 0.f, 0.f);
#pragma unroll
    for (int q = 0; q < HID/4; q++) g_s2_4[(size_t)n * (HID/4) + q] = z4;
}

// ---------------- kernel 2: edge pass 1 (binary feature scatter) -----------
__global__ void k_edge1(const void* __restrict__ ei) {
    int e = blockIdx.x * blockDim.x + threadIdx.x;
    if (e >= N_EDGES) return;
    int is64 = g_is64;
    int r, c;
    edge_rc(ei, e, is64, r, c);
    unsigned m = g_mask[r];
    unsigned long long w0 = spread8( m         & 0xffu);
    unsigned long long w1 = spread8((m >>  8)  & 0xffu);
    unsigned long long w2 = spread8((m >> 16)  & 0xffu);
    atomicAdd(&g_cnt[3*c + 0], w0);
    atomicAdd(&g_cnt[3*c + 1], w1);
    atomicAdd(&g_cnt[3*c + 2], w2);
    atomicAdd(&g_deg[c], 1);
}

// ---------------- kernel 3: node pass 1 (SAGE layer 1 -> h) ----------------
__global__ __launch_bounds__(128)
void k_node1(const float* __restrict__ w1l, const float* __restrict__ b1,
             const float* __restrict__ w1r) {
    __shared__ float s_l[HID*M], s_r[HID*M], s_b[HID];
    for (int i = threadIdx.x; i < HID*M; i += blockDim.x) {
        s_l[i] = w1l[i];
        s_r[i] = w1r[i];
    }
    for (int i = threadIdx.x; i < HID; i += blockDim.x) s_b[i] = b1[i];
    __syncthreads();

    int n = blockIdx.x * blockDim.x + threadIdx.x;
    if (n >= N_NODES) return;

    unsigned m = g_mask[n];
    int deg = g_deg[n];
    float inv = 1.0f / (float)(deg > 0 ? deg : 1);
    unsigned long long w[3];
    w[0] = g_cnt[3*n + 0];
    w[1] = g_cnt[3*n + 1];
    w[2] = g_cnt[3*n + 2];

    float ff[M], fx[M];
#pragma unroll
    for (int j = 0; j < M; j++) {
        int g = j >> 3, jj = j & 7;
        unsigned c = (unsigned)((w[g] >> (8 * (7 - jj))) & 0xffULL);
        ff[j] = (float)c * inv;
        fx[j] = (float)((m >> j) & 1u);
    }

    float hrow[HID];
#pragma unroll
    for (int i = 0; i < HID; i++) {
        float a = s_b[i];
#pragma unroll
        for (int j = 0; j < M; j++)
            a += ff[j] * s_l[i*M + j] + fx[j] * s_r[i*M + j];
        hrow[i] = fmaxf(a, 0.0f);
    }
    float4* hr4 = &g_h4[(size_t)n * (HID/4)];
#pragma unroll
    for (int q = 0; q < HID/4; q++)
        hr4[q] = make_float4(hrow[4*q+0], hrow[4*q+1], hrow[4*q+2], hrow[4*q+3]);
}

// ---------------- kernel 4: edge pass 2 (h scatter, v4 REDs) ---------------
__global__ void k_edge2(const void* __restrict__ ei) {
    int e = blockIdx.x * blockDim.x + threadIdx.x;
    if (e >= N_EDGES) return;
    int is64 = g_is64;
    int r, c;
    edge_rc(ei, e, is64, r, c);
    const float4* hr = &g_h4[(size_t)r * (HID/4)];
    float4*       sd = &g_s2_4[(size_t)c * (HID/4)];
#pragma unroll
    for (int q = 0; q < HID/4; q++) {
        float4 v = hr[q];
        asm volatile("red.global.add.v4.f32 [%0], {%1, %2, %3, %4};"
                     :: "l"(sd + q), "f"(v.x), "f"(v.y), "f"(v.z), "f"(v.w)
                     : "memory");
    }
}

// ---------------- kernel 5: node pass 2 (layer 2 + feats + head) -----------
__global__ __launch_bounds__(128)
void k_node2(const float* __restrict__ w2l, const float* __restrict__ b2,
             const float* __restrict__ w2r, const float* __restrict__ hw,
             const float* __restrict__ hb, float* __restrict__ out,
             int write_z) {
    __shared__ float s_l[OUT*HID], s_r[OUT*HID], s_b[OUT], s_hw[ZC], s_hb;
    for (int i = threadIdx.x; i < OUT*HID; i += blockDim.x) {
        s_l[i] = w2l[i];
        s_r[i] = w2r[i];
    }
    for (int i = threadIdx.x; i < OUT; i += blockDim.x) s_b[i] = b2[i];
    for (int i = threadIdx.x; i < ZC;  i += blockDim.x) s_hw[i] = hw[i];
    if (threadIdx.x == 0) s_hb = hb[0];
    __syncthreads();

    int n = blockIdx.x * blockDim.x + threadIdx.x;
    if (n >= N_NODES) return;

    unsigned m = g_mask[n];
    int deg = g_deg[n];
    float inv = 1.0f / (float)(deg > 0 ? deg : 1);
    unsigned long long w[3];
    w[0] = g_cnt[3*n + 0];
    w[1] = g_cnt[3*n + 1];
    w[2] = g_cnt[3*n + 2];

    float y = s_hb;
    float4* zrow = (float4*)(out + N_NODES + (size_t)n * ZC);

    float ff[M];
#pragma unroll
    for (int j = 0; j < M; j++) {
        int g = j >> 3, jj = j & 7;
        unsigned c = (unsigned)((w[g] >> (8 * (7 - jj))) & 0xffULL);
        ff[j] = (float)c * inv;
    }
#pragma unroll
    for (int q = 0; q < M/4; q++) {
        float x0 = (float)((m >> (4*q+0)) & 1u);
        float x1 = (float)((m >> (4*q+1)) & 1u);
        float x2 = (float)((m >> (4*q+2)) & 1u);
        float x3 = (float)((m >> (4*q+3)) & 1u);
        float f0 = ff[4*q+0], f1 = ff[4*q+1], f2 = ff[4*q+2], f3 = ff[4*q+3];
        if (write_z) {
            zrow[q]           = make_float4(x0, x1, x2, x3);
            zrow[M/4 + q]     = make_float4(f0, f1, f2, f3);
            zrow[2*(M/4) + q] = make_float4(x0*f0, x1*f1, x2*f2, x3*f3);
        }
        y += x0*s_hw[4*q+0] + x1*s_hw[4*q+1] + x2*s_hw[4*q+2] + x3*s_hw[4*q+3];
        y += f0*s_hw[M+4*q+0] + f1*s_hw[M+4*q+1] + f2*s_hw[M+4*q+2] + f3*s_hw[M+4*q+3];
        y += x0*f0*s_hw[2*M+4*q+0] + x1*f1*s_hw[2*M+4*q+1]
           + x2*f2*s_hw[2*M+4*q+2] + x3*f3*s_hw[2*M+4*q+3];
    }

    float hrow[HID], ag[HID];
    const float4* h4 = &g_h4[(size_t)n * (HID/4)];
    const float4* s4 = &g_s2_4[(size_t)n * (HID/4)];
#pragma unroll
    for (int q = 0; q < HID/4; q++) {
        float4 hv = h4[q], sv = s4[q];
        hrow[4*q+0] = hv.x; hrow[4*q+1] = hv.y; hrow[4*q+2] = hv.z; hrow[4*q+3] = hv.w;
        ag[4*q+0] = sv.x*inv; ag[4*q+1] = sv.y*inv; ag[4*q+2] = sv.z*inv; ag[4*q+3] = sv.w*inv;
    }

    float emb[OUT];
#pragma unroll
    for (int i = 0; i < OUT; i++) {
        float a = s_b[i];
#pragma unroll
        for (int j = 0; j < HID; j++)
            a += ag[j] * s_l[i*HID + j] + hrow[j] * s_r[i*HID + j];
        a = fmaxf(a, 0.0f);
        emb[i] = a;
        y += a * s_hw[3*M + i];
    }
    if (write_z) {
#pragma unroll
        for (int q = 0; q < OUT/4; q++)
            zrow[3*(M/4) + q] = make_float4(emb[4*q+0], emb[4*q+1], emb[4*q+2], emb[4*q+3]);
    }

    out[n] = y;
}

// ---------------- launch --------------------------------------------------
extern "C" void kernel_launch(void* const* d_in, const int* in_sizes, int n_in,
                              void* d_out, int out_size) {
    const float* x_bin = (const float*)d_in[0];
    const void*  ei    = d_in[1];
    const float* w1l   = (const float*)d_in[2];
    const float* b1    = (const float*)d_in[3];
    const float* w1r   = (const float*)d_in[4];
    const float* w2l   = (const float*)d_in[5];
    const float* b2    = (const float*)d_in[6];
    const float* w2r   = (const float*)d_in[7];
    const float* hw    = (const float*)d_in[8];
    const float* hb    = (const float*)d_in[9];
    float* out = (float*)d_out;

    int write_z = (out_size >= N_NODES + N_NODES * ZC) ? 1 : 0;

    int nb_n256 = (N_NODES + 255) / 256;
    int nb_n128 = (N_NODES + 127) / 128;
    int nb_e    = (N_EDGES + 255) / 256;

    k_probe<<<1, 1>>>((const long long*)ei);
    k_init <<<nb_n256, 256>>>(x_bin);
    k_edge1<<<nb_e,    256>>>(ei);
    k_node1<<<nb_n128, 128>>>(w1l, b1, w1r);
    k_edge2<<<nb_e,    256>>>(ei);
    k_node2<<<nb_n128, 128>>>(w2l, b2, w2r, hw, hb, out, write_z);
}